// round 10
// baseline (speedup 1.0000x reference)
#include <cuda_runtime.h>
#include <cuda_bf16.h>
#include <cstdint>

// Fixed problem geometry (reference: H_IMG=352, W_IMG=640, item=0)
#define H_IMG 352
#define W_IMG 640
#define NPIX  (H_IMG * W_IMG)

// Complement-encoded z-buffer: cell = ~((z_bits << 32) | idx), 0 = empty.
// atomicMax(~packed) == atomicMin(packed). Zero is the natural .bss init
// AND what render restores after reading, so NO memset node is needed:
// the buffer is self-resetting across kernel_launch calls / graph replays.
__device__ unsigned long long g_zidx[NPIX];   // zero-initialized at load

// 1 point/thread. Bound by the irreducible ~1 random L2 atomic per
// in-bounds point; math/load-form proven irrelevant across rounds 2-8.
__global__ void splat_kernel(const float* __restrict__ means,
                             const float* __restrict__ Kmat,
                             const float* __restrict__ E,
                             int N) {
    int i = blockIdx.x * blockDim.x + threadIdx.x;
    if (i >= N) return;

    float x = means[3 * i + 0];
    float y = means[3 * i + 1];
    float zc = means[3 * i + 2];

    // pts_c = R @ p + t, R = E[:3,:3], t = E[:3,3] (row-major 4x4)
    float px = E[0] * x + E[1] * y + E[2]  * zc + E[3];
    float py = E[4] * x + E[5] * y + E[6]  * zc + E[7];
    float pz = E[8] * x + E[9] * y + E[10] * zc + E[11];

    bool valid = pz > 0.1f;
    float zsafe = valid ? pz : 1.0f;

    float fx = Kmat[0], cx = Kmat[2];
    float fy = Kmat[4], cy = Kmat[5];

    // Exact rn division + un-fused mul/add so int truncation boundaries
    // match the reference's unfused f32 ops.
    float ru = __fdiv_rn(px, zsafe);
    float rv = __fdiv_rn(py, zsafe);
    float uf = __fadd_rn(__fmul_rn(ru, fx), cx);
    float vf = __fadd_rn(__fmul_rn(rv, fy), cy);
    int u = (int)uf;   // trunc toward zero, matches astype(int32)
    int v = (int)vf;

    bool inb = valid & (u >= 0) & (u < W_IMG) & (v >= 0) & (v < H_IMG);
    if (!inb) return;

    int pix = v * W_IMG + u;
    unsigned long long packed =
        ((unsigned long long)__float_as_uint(pz) << 32) | (unsigned int)i;
    atomicMax(&g_zidx[pix], ~packed);
}

__device__ __forceinline__ float fast_sigmoid(float x) {
    return __frcp_rn(1.0f + __expf(-x));
}

// 1 pixel/thread. Reads the complemented cell, writes 0 back (self-reset,
// replaces the memset node), float4 colour gather, coalesced plane writes.
__global__ void __launch_bounds__(256)
render_kernel(const float* __restrict__ colours,
              float* __restrict__ out) {
    int p = blockIdx.x * blockDim.x + threadIdx.x;
    if (p >= NPIX) return;

    unsigned long long v = __ldcg(&g_zidx[p]);
    g_zidx[p] = 0ULL;   // restore empty state for the next call/replay

    float r = 0.f, g = 0.f, b = 0.f;
    if (v != 0ULL) {
        unsigned long long packed = ~v;
        unsigned int idx = (unsigned int)(packed & 0xFFFFFFFFULL);
        float4 c = *reinterpret_cast<const float4*>(colours + (size_t)idx * 12);
        r = fast_sigmoid(c.x);
        g = fast_sigmoid(c.y);
        b = fast_sigmoid(c.z);
    }
    out[p]            = r;
    out[NPIX + p]     = g;
    out[2 * NPIX + p] = b;
}

extern "C" void kernel_launch(void* const* d_in, const int* in_sizes, int n_in,
                              void* d_out, int out_size) {
    const float* means   = (const float*)d_in[0];  // [N,3]
    const float* colours = (const float*)d_in[1];  // [N,12]
    const float* Kmat    = (const float*)d_in[2];  // [3,3]
    const float* E       = (const float*)d_in[3];  // [4,4]
    float* out = (float*)d_out;                    // [3,H,W]

    int N = in_sizes[0] / 3;

    const int TPB = 256;
    splat_kernel<<<(N + TPB - 1) / TPB, TPB>>>(means, Kmat, E, N);
    render_kernel<<<(NPIX + TPB - 1) / TPB, TPB>>>(colours, out);
}

// round 11
// speedup vs baseline: 1.1150x; 1.1150x over previous
#include <cuda_runtime.h>
#include <cuda_bf16.h>
#include <cstdint>

// Fixed problem geometry (reference: H_IMG=352, W_IMG=640, item=0)
#define H_IMG 352
#define W_IMG 640
#define NPIX  (H_IMG * W_IMG)
// NPIX = 225280 = 880 * 256 exactly; NPIX/2 = 112640 = 440 * 256 exactly.

// Double-buffered complement-encoded z-buffer.
// cell = ~((z_bits << 32) | idx), 0 = empty; atomicMax(~p) == atomicMin(p).
// buf[g_flip] is clean at the start of every execution: first call uses the
// .bss zeros; every call zeroes buf[g_flip^1] inside splat (race-free: this
// call's atomics only touch buf[g_flip]); render's last block flips g_flip.
__device__ __align__(16) unsigned long long g_zbuf[2][NPIX];  // .bss zeros
__device__ unsigned int g_flip;   // current buffer index (starts 0)
__device__ unsigned int g_done;   // render completion counter (starts 0)

// 1 point/thread (proven optimal shape). Also zeroes the other buffer:
// threads 0..NPIX/2-1 each store one zero ulonglong2 (16B).
__global__ void splat_kernel(const float* __restrict__ means,
                             const float* __restrict__ Kmat,
                             const float* __restrict__ E,
                             int N) {
    int i = blockIdx.x * blockDim.x + threadIdx.x;
    unsigned int f = g_flip;

    // Hidden re-init of the other buffer (next call's clean buffer).
    if (i < NPIX / 2) {
        ulonglong2 zz; zz.x = 0ULL; zz.y = 0ULL;
        reinterpret_cast<ulonglong2*>(g_zbuf[f ^ 1u])[i] = zz;
    }

    if (i >= N) return;

    float x = means[3 * i + 0];
    float y = means[3 * i + 1];
    float zc = means[3 * i + 2];

    // pts_c = R @ p + t, R = E[:3,:3], t = E[:3,3] (row-major 4x4)
    float px = E[0] * x + E[1] * y + E[2]  * zc + E[3];
    float py = E[4] * x + E[5] * y + E[6]  * zc + E[7];
    float pz = E[8] * x + E[9] * y + E[10] * zc + E[11];

    bool valid = pz > 0.1f;
    float zsafe = valid ? pz : 1.0f;

    float fx = Kmat[0], cx = Kmat[2];
    float fy = Kmat[4], cy = Kmat[5];

    // Exact rn division + un-fused mul/add so int truncation boundaries
    // match the reference's unfused f32 ops.
    float ru = __fdiv_rn(px, zsafe);
    float rv = __fdiv_rn(py, zsafe);
    float uf = __fadd_rn(__fmul_rn(ru, fx), cx);
    float vf = __fadd_rn(__fmul_rn(rv, fy), cy);
    int u = (int)uf;   // trunc toward zero, matches astype(int32)
    int v = (int)vf;

    bool inb = valid & (u >= 0) & (u < W_IMG) & (v >= 0) & (v < H_IMG);
    if (!inb) return;

    int pix = v * W_IMG + u;
    unsigned long long packed =
        ((unsigned long long)__float_as_uint(pz) << 32) | (unsigned int)i;
    atomicMax(&g_zbuf[f][pix], ~packed);
}

__device__ __forceinline__ float fast_sigmoid(float x) {
    return __frcp_rn(1.0f + __expf(-x));
}

// 1 pixel/thread, no reset store (critical path untouched). Grid is exactly
// NPIX/256 blocks; no early returns so the completion protocol is safe.
// The last block to finish flips g_flip for the next execution — after every
// block has already read the flag and completed its work.
__global__ void __launch_bounds__(256)
render_kernel(const float* __restrict__ colours,
              float* __restrict__ out) {
    int p = blockIdx.x * blockDim.x + threadIdx.x;
    unsigned int f = g_flip;

    unsigned long long v = __ldcg(&g_zbuf[f][p]);
    float r = 0.f, g = 0.f, b = 0.f;
    if (v != 0ULL) {
        unsigned long long packed = ~v;
        unsigned int idx = (unsigned int)(packed & 0xFFFFFFFFULL);
        float4 c = *reinterpret_cast<const float4*>(colours + (size_t)idx * 12);
        r = fast_sigmoid(c.x);
        g = fast_sigmoid(c.y);
        b = fast_sigmoid(c.z);
    }
    out[p]            = r;
    out[NPIX + p]     = g;
    out[2 * NPIX + p] = b;

    __syncthreads();
    if (threadIdx.x == 0) {
        unsigned int done = atomicAdd(&g_done, 1u);
        if (done == gridDim.x - 1) {   // last block: all blocks ran already
            g_done = 0u;
            g_flip = f ^ 1u;           // next execution uses the clean buffer
        }
    }
}

extern "C" void kernel_launch(void* const* d_in, const int* in_sizes, int n_in,
                              void* d_out, int out_size) {
    const float* means   = (const float*)d_in[0];  // [N,3]
    const float* colours = (const float*)d_in[1];  // [N,12]
    const float* Kmat    = (const float*)d_in[2];  // [3,3]
    const float* E       = (const float*)d_in[3];  // [4,4]
    float* out = (float*)d_out;                    // [3,H,W]

    int N = in_sizes[0] / 3;

    const int TPB = 256;
    splat_kernel<<<(N + TPB - 1) / TPB, TPB>>>(means, Kmat, E, N);
    render_kernel<<<NPIX / TPB, TPB>>>(colours, out);
}